// round 2
// baseline (speedup 1.0000x reference)
#include <cuda_runtime.h>
#include <math.h>
#include <stdint.h>

#define N 3072
#define D 256
#define H 8
#define DH 32

// ---------------- scratch (static device allocations; no cudaMalloc) ----------------
__device__ float g_q[N * D];
__device__ float g_k[N * D];
__device__ float g_v[N * D];
__device__ float g_feat[N * D];
__device__ float g_S[8ull * 3072ull * 3072ull];   // [H][N][N] scores
__device__ float g_bias[3072ull * 3072ull];       // -delta_y (valid) or -1e30
__device__ float g_xyz[2][N * 3];
__device__ float g_mx[H * N];
__device__ float g_sum[H * N];
__device__ int   g_mask_mode;                     // 0=int32, 1=float32, 2=uint8

// ---------------- mask dtype detection ----------------
// int32 0/1: bytes at offset 1 and 3 (mod 4) are all zero.
// float32 0.0/1.0: byte offset 1 always zero, byte offset 3 nonzero for 1.0 (0x3F).
// uint8 0/1: bytes at every offset can be nonzero (mask ~90% true).
__global__ void detect_kernel(const unsigned char* __restrict__ p) {
    __shared__ int c1, c3;
    int t = threadIdx.x;
    if (t == 0) { c1 = 0; c3 = 0; }
    __syncthreads();
    int l1 = 0, l3 = 0;
    for (int i = t; i < 16384; i += 256) {
        l1 += (p[i * 4 + 1] != 0);
        l3 += (p[i * 4 + 3] != 0);
    }
    atomicAdd(&c1, l1);
    atomicAdd(&c3, l3);
    __syncthreads();
    if (t == 0) {
        g_mask_mode = (c3 == 0) ? 0 : ((c1 == 0) ? 1 : 2);
    }
}

// ---------------- bias build: B[n,m] = valid ? -delta_y : -1e30 ----------------
__global__ __launch_bounds__(256) void bias_kernel(const float* __restrict__ dy,
                                                   const void* __restrict__ dm,
                                                   const void* __restrict__ bim) {
    int n = blockIdx.x;
    int mode = g_mask_mode;
    size_t row = (size_t)n * N;
    for (int m = threadIdx.x; m < N; m += 256) {
        bool a, b;
        if (mode == 0) {
            a = ((const int*)dm)[row + m] != 0;
            b = ((const int*)bim)[row + m] != 0;
        } else if (mode == 1) {
            a = ((const float*)dm)[row + m] != 0.0f;
            b = ((const float*)bim)[row + m] != 0.0f;
        } else {
            a = ((const unsigned char*)dm)[row + m] != 0;
            b = ((const unsigned char*)bim)[row + m] != 0;
        }
        bool valid = (a && b) || (m == n);
        g_bias[row + m] = valid ? -dy[row + m] : -1e30f;
    }
}

// ---------------- generic tiled GEMM: C = A[MxK] @ W[KxNN] + bias (+resid) ----------------
__global__ __launch_bounds__(256) void gemm64(const float* __restrict__ A,
                                              const float* __restrict__ W,
                                              const float* __restrict__ bias,
                                              const float* __restrict__ resid,
                                              float* __restrict__ C,
                                              int M, int K, int NN) {
    __shared__ float As[16][65];
    __shared__ float Ws[16][65];
    int t = threadIdx.x;
    int tx = t & 15, ty = t >> 4;
    int n0 = blockIdx.x * 64, m0 = blockIdx.y * 64;
    float acc[4][4] = {};
    for (int kt = 0; kt < K; kt += 16) {
        #pragma unroll
        for (int i = 0; i < 4; i++) {
            int idx = i * 256 + t;
            int r = idx >> 4, kk = idx & 15;
            As[kk][r] = A[(size_t)(m0 + r) * K + kt + kk];
        }
        #pragma unroll
        for (int i = 0; i < 4; i++) {
            int idx = i * 256 + t;
            int kk = idx >> 6, j = idx & 63;
            Ws[kk][j] = W[(size_t)(kt + kk) * NN + n0 + j];
        }
        __syncthreads();
        #pragma unroll
        for (int kk = 0; kk < 16; kk++) {
            float a[4], b[4];
            #pragma unroll
            for (int i = 0; i < 4; i++) a[i] = As[kk][ty * 4 + i];
            #pragma unroll
            for (int j = 0; j < 4; j++) b[j] = Ws[kk][tx * 4 + j];
            #pragma unroll
            for (int i = 0; i < 4; i++)
                #pragma unroll
                for (int j = 0; j < 4; j++)
                    acc[i][j] += a[i] * b[j];
        }
        __syncthreads();
    }
    #pragma unroll
    for (int i = 0; i < 4; i++) {
        int row = m0 + ty * 4 + i;
        #pragma unroll
        for (int j = 0; j < 4; j++) {
            int col = n0 + tx * 4 + j;
            float v = acc[i][j] + bias[col];
            if (resid) v += resid[(size_t)row * NN + col];
            C[(size_t)row * NN + col] = v;
        }
    }
}

// ---------------- scores: S[h,n,m] = q[n,h,:]·k[m,h,:] / sqrt(32) ----------------
__global__ __launch_bounds__(256) void score_kernel() {
    __shared__ float Qs[32][68];
    __shared__ float Ks[32][68];
    int t = threadIdx.x;
    int h = blockIdx.z;
    int n0 = blockIdx.y * 64, m0 = blockIdx.x * 64;
    #pragma unroll
    for (int i = 0; i < 8; i++) {
        int idx = i * 256 + t;
        int r = idx >> 5, d = idx & 31;
        Qs[d][r] = g_q[(size_t)(n0 + r) * D + h * DH + d];
        Ks[d][r] = g_k[(size_t)(m0 + r) * D + h * DH + d];
    }
    __syncthreads();
    int tx = t & 15, ty = t >> 4;
    float acc[4][4] = {};
    #pragma unroll
    for (int d = 0; d < 32; d++) {
        float4 a = *(const float4*)&Qs[d][ty * 4];
        float4 b = *(const float4*)&Ks[d][tx * 4];
        float av[4] = {a.x, a.y, a.z, a.w};
        float bv[4] = {b.x, b.y, b.z, b.w};
        #pragma unroll
        for (int i = 0; i < 4; i++)
            #pragma unroll
            for (int j = 0; j < 4; j++)
                acc[i][j] += av[i] * bv[j];
    }
    const float sc = 0.17677669529663689f;  // 1/sqrt(32)
    #pragma unroll
    for (int i = 0; i < 4; i++) {
        int r = n0 + ty * 4 + i;
        float4 o;
        o.x = acc[i][0] * sc; o.y = acc[i][1] * sc;
        o.z = acc[i][2] * sc; o.w = acc[i][3] * sc;
        *(float4*)&g_S[((size_t)h * N + r) * N + m0 + tx * 4] = o;
    }
}

// ---------------- one mean-shift iteration: xyz update (+ optional stats save) ----------------
__global__ __launch_bounds__(256) void iter_kernel(const float* __restrict__ xin,
                                                   float* __restrict__ xout,
                                                   int save) {
    __shared__ float xs[N * 3];
    __shared__ float wred[H][3];
    int t = threadIdx.x;
    for (int i = t; i < N * 3; i += 256) xs[i] = xin[i];
    __syncthreads();

    int h = t >> 5, lane = t & 31;
    int n = blockIdx.x;
    float xnx = xs[n * 3], xny = xs[n * 3 + 1], xnz = xs[n * 3 + 2];
    const float* __restrict__ Srow = g_S + ((size_t)h * N + n) * N;
    const float* __restrict__ Brow = g_bias + (size_t)n * N;

    float mx = -INFINITY, sm = 0.f, ax = 0.f, ay = 0.f, az = 0.f;
    for (int m = lane; m < N; m += 32) {
        float bx = xs[m * 3], by = xs[m * 3 + 1], bz = xs[m * 3 + 2];
        float dx = xnx - bx, dy = xny - by, dz = xnz - bz;
        float d2 = dx * dx + dy * dy + dz * dz;
        if (m == n) d2 = 1e-4f;  // SELF_DISTANCE^2
        float lg = Srow[m] + Brow[m] - 0.25f * d2;  // T=1, BETA*inv2bw2=0.25
        if (lg > mx) {
            float c = __expf(mx - lg);
            sm = sm * c + 1.f;
            ax = ax * c + bx; ay = ay * c + by; az = az * c + bz;
            mx = lg;
        } else {
            float p = __expf(lg - mx);
            sm += p; ax += p * bx; ay += p * by; az += p * bz;
        }
    }
    // warp-level log-sum-exp merge
    #pragma unroll
    for (int o = 16; o; o >>= 1) {
        float mx2 = __shfl_xor_sync(0xffffffffu, mx, o);
        float sm2 = __shfl_xor_sync(0xffffffffu, sm, o);
        float ax2 = __shfl_xor_sync(0xffffffffu, ax, o);
        float ay2 = __shfl_xor_sync(0xffffffffu, ay, o);
        float az2 = __shfl_xor_sync(0xffffffffu, az, o);
        float M = fmaxf(mx, mx2);
        float c1 = __expf(mx - M), c2 = __expf(mx2 - M);
        sm = sm * c1 + sm2 * c2;
        ax = ax * c1 + ax2 * c2;
        ay = ay * c1 + ay2 * c2;
        az = az * c1 + az2 * c2;
        mx = M;
    }
    if (lane == 0) {
        if (save) { g_mx[h * N + n] = mx; g_sum[h * N + n] = sm; }
        float inv = 1.f / sm;
        wred[h][0] = ax * inv; wred[h][1] = ay * inv; wred[h][2] = az * inv;
    }
    __syncthreads();
    if (t < 3) {
        float s = 0.f;
        #pragma unroll
        for (int hh = 0; hh < H; hh++) s += wred[hh][t];
        xout[n * 3 + t] = s * 0.125f;  // mean over 8 heads
    }
}

// ---------------- feat = softmax(logits) @ V, P recomputed on the fly ----------------
__global__ __launch_bounds__(256) void feat_kernel(const float* __restrict__ xyz) {
    __shared__ float Ps[128][65];
    __shared__ float Vs[64][36];
    __shared__ float xr[128 * 3];
    __shared__ float xc[64 * 3];
    __shared__ float mxs[128];
    __shared__ float sms[128];
    int t = threadIdx.x;
    int h = blockIdx.y;
    int n0 = blockIdx.x * 128;

    if (t < 128) {
        mxs[t] = g_mx[h * N + n0 + t];
        sms[t] = g_sum[h * N + n0 + t];
    }
    for (int i = t; i < 384; i += 256) xr[i] = xyz[n0 * 3 + i];

    int dg = t & 7, rg = t >> 3;
    int d4 = dg * 4, r0 = rg * 4;
    float acc[4][4] = {};

    for (int mb = 0; mb < N; mb += 64) {
        __syncthreads();  // previous compute done
        for (int i = t; i < 192; i += 256) xc[i] = xyz[mb * 3 + i];
        #pragma unroll
        for (int i = 0; i < 8; i++) {
            int idx = i * 256 + t;
            int j = idx >> 5, d = idx & 31;
            Vs[j][d] = g_v[(size_t)(mb + j) * D + h * DH + d];
        }
        __syncthreads();  // xc / Vs ready
        for (int i = 0; i < 32; i++) {
            int idx = i * 256 + t;
            int r = idx >> 6, j = idx & 63;
            int m = mb + j;
            float s = g_S[((size_t)h * N + n0 + r) * N + m] +
                      g_bias[(size_t)(n0 + r) * N + m];
            float dx = xr[r * 3] - xc[j * 3];
            float dy = xr[r * 3 + 1] - xc[j * 3 + 1];
            float dz = xr[r * 3 + 2] - xc[j * 3 + 2];
            float d2 = dx * dx + dy * dy + dz * dz;
            if (n0 + r == m) d2 = 1e-4f;
            Ps[r][j] = __expf(s - 0.25f * d2 - mxs[r]);
        }
        __syncthreads();  // Ps ready
        #pragma unroll 2
        for (int j = 0; j < 64; j++) {
            float4 v = *(const float4*)&Vs[j][d4];
            #pragma unroll
            for (int i = 0; i < 4; i++) {
                float p = Ps[r0 + i][j];
                acc[i][0] += p * v.x;
                acc[i][1] += p * v.y;
                acc[i][2] += p * v.z;
                acc[i][3] += p * v.w;
            }
        }
    }
    #pragma unroll
    for (int i = 0; i < 4; i++) {
        int row = n0 + r0 + i;
        float inv = 1.f / sms[r0 + i];
        float4 o;
        o.x = acc[i][0] * inv; o.y = acc[i][1] * inv;
        o.z = acc[i][2] * inv; o.w = acc[i][3] * inv;
        *(float4*)&g_feat[(size_t)row * D + h * DH + d4] = o;
    }
}

// ---------------- launch ----------------
extern "C" void kernel_launch(void* const* d_in, const int* in_sizes, int n_in,
                              void* d_out, int out_size) {
    const float* x   = (const float*)d_in[0];
    const float* xyz = (const float*)d_in[1];
    const float* dy  = (const float*)d_in[2];
    const void*  dm  = d_in[3];
    const void*  bim = d_in[4];
    const float* Wq = (const float*)d_in[5];
    const float* bq = (const float*)d_in[6];
    const float* Wk = (const float*)d_in[7];
    const float* bk = (const float*)d_in[8];
    const float* Wv = (const float*)d_in[9];
    const float* bv = (const float*)d_in[10];
    const float* Wo = (const float*)d_in[11];
    const float* bo = (const float*)d_in[12];
    float* out = (float*)d_out;

    float *q, *k, *v, *feat, *xb;
    cudaGetSymbolAddress((void**)&q, g_q);
    cudaGetSymbolAddress((void**)&k, g_k);
    cudaGetSymbolAddress((void**)&v, g_v);
    cudaGetSymbolAddress((void**)&feat, g_feat);
    cudaGetSymbolAddress((void**)&xb, g_xyz);
    float* xbuf0 = xb;
    float* xbuf1 = xb + N * 3;

    // output layout handling: tuple (xyz_out, out) flattened+concatenated by default
    float* xyz_dst = xbuf0;  // fallback (reused scratch)
    float* out_dst = out;
    if (out_size == N * 3 + N * D) { xyz_dst = out; out_dst = out + N * 3; }
    else if (out_size == N * D)    { out_dst = out; }
    else if (out_size == N * 3)    { xyz_dst = out; out_dst = feat; /* discard */ }

    detect_kernel<<<1, 256>>>((const unsigned char*)bim);
    bias_kernel<<<N, 256>>>(dy, dm, bim);

    dim3 gproj(4, 48);
    gemm64<<<gproj, 256>>>(x, Wq, bq, nullptr, q, N, D, D);
    gemm64<<<gproj, 256>>>(x, Wk, bk, nullptr, k, N, D, D);
    gemm64<<<gproj, 256>>>(x, Wv, bv, nullptr, v, N, D, D);

    score_kernel<<<dim3(48, 48, 8), 256>>>();

    iter_kernel<<<N, 256>>>(xyz, xbuf0, 0);
    iter_kernel<<<N, 256>>>(xbuf0, xbuf1, 0);
    iter_kernel<<<N, 256>>>(xbuf1, xyz_dst, 1);  // stats computed w.r.t. xbuf1 (xyz after 2 iters)

    feat_kernel<<<dim3(24, 8), 256>>>(xbuf1);

    gemm64<<<gproj, 256>>>(feat, Wo, bo, x, out_dst, N, D, D);
}

// round 4
// speedup vs baseline: 2.2663x; 2.2663x over previous
#include <cuda_runtime.h>
#include <math.h>
#include <stdint.h>

#define N 3072
#define D 256
#define H 8
#define DH 32
#define QKV 768

// ---------------- scratch ----------------
__device__ float g_qkv[N * QKV];                  // [N][q(256) | k(256) | v(256)]
__device__ float g_Wqkv[D * QKV];
__device__ float g_bqkv[QKV];
__device__ float g_feat[N * D];
__device__ float g_S[8ull * 3072ull * 3072ull];   // scores+bias, then P (iter3)
__device__ float g_bias[3072ull * 3072ull];
__device__ float g_xyz[2][N * 3];
__device__ float g_sum[H * N];
__device__ int   g_mask_mode;

// ---------------- mask dtype detection ----------------
__global__ void detect_kernel(const unsigned char* __restrict__ p) {
    __shared__ int c1, c3;
    int t = threadIdx.x;
    if (t == 0) { c1 = 0; c3 = 0; }
    __syncthreads();
    int l1 = 0, l3 = 0;
    for (int i = t; i < 16384; i += 256) {
        l1 += (p[i * 4 + 1] != 0);
        l3 += (p[i * 4 + 3] != 0);
    }
    atomicAdd(&c1, l1);
    atomicAdd(&c3, l3);
    __syncthreads();
    if (t == 0) g_mask_mode = (c3 == 0) ? 0 : ((c1 == 0) ? 1 : 2);
}

// ---------------- bias: B[n,m] = valid ? -delta_y : -1e30 ----------------
__global__ __launch_bounds__(256) void bias_kernel(const float* __restrict__ dy,
                                                   const void* __restrict__ dm,
                                                   const void* __restrict__ bim) {
    int n = blockIdx.x;
    int mode = g_mask_mode;
    size_t row = (size_t)n * N;
    for (int m = threadIdx.x; m < N; m += 256) {
        bool a, b;
        if (mode == 0) {
            a = ((const int*)dm)[row + m] != 0;
            b = ((const int*)bim)[row + m] != 0;
        } else if (mode == 1) {
            a = ((const float*)dm)[row + m] != 0.0f;
            b = ((const float*)bim)[row + m] != 0.0f;
        } else {
            a = ((const unsigned char*)dm)[row + m] != 0;
            b = ((const unsigned char*)bim)[row + m] != 0;
        }
        bool valid = (a && b) || (m == n);
        g_bias[row + m] = valid ? -dy[row + m] : -1e30f;
    }
}

// ---------------- pack [Wq|Wk|Wv] and biases ----------------
__global__ __launch_bounds__(256) void pack_kernel(const float* __restrict__ Wq,
                                                   const float* __restrict__ Wk,
                                                   const float* __restrict__ Wv,
                                                   const float* __restrict__ bq,
                                                   const float* __restrict__ bk,
                                                   const float* __restrict__ bv) {
    int idx = blockIdx.x * 256 + threadIdx.x;  // 0..65535
    int row = idx >> 8, col = idx & 255;
    g_Wqkv[row * QKV + col]       = Wq[idx];
    g_Wqkv[row * QKV + 256 + col] = Wk[idx];
    g_Wqkv[row * QKV + 512 + col] = Wv[idx];
    if (idx < 256) {
        g_bqkv[idx]       = bq[idx];
        g_bqkv[256 + idx] = bk[idx];
        g_bqkv[512 + idx] = bv[idx];
    }
}

// ---------------- generic tiled GEMM: C = A[MxK] @ W[KxNN] + bias (+resid) ----------------
__global__ __launch_bounds__(256) void gemm64(const float* __restrict__ A,
                                              const float* __restrict__ W,
                                              const float* __restrict__ bias,
                                              const float* __restrict__ resid,
                                              float* __restrict__ C,
                                              int M, int K, int NN) {
    __shared__ float As[16][65];
    __shared__ float Ws[16][65];
    int t = threadIdx.x;
    int tx = t & 15, ty = t >> 4;
    int n0 = blockIdx.x * 64, m0 = blockIdx.y * 64;
    float acc[4][4] = {};
    for (int kt = 0; kt < K; kt += 16) {
        #pragma unroll
        for (int i = 0; i < 4; i++) {
            int idx = i * 256 + t;
            int r = idx >> 4, kk = idx & 15;
            As[kk][r] = A[(size_t)(m0 + r) * K + kt + kk];
        }
        #pragma unroll
        for (int i = 0; i < 4; i++) {
            int idx = i * 256 + t;
            int kk = idx >> 6, j = idx & 63;
            Ws[kk][j] = W[(size_t)(kt + kk) * NN + n0 + j];
        }
        __syncthreads();
        #pragma unroll
        for (int kk = 0; kk < 16; kk++) {
            float a[4], b[4];
            #pragma unroll
            for (int i = 0; i < 4; i++) a[i] = As[kk][ty * 4 + i];
            #pragma unroll
            for (int j = 0; j < 4; j++) b[j] = Ws[kk][tx * 4 + j];
            #pragma unroll
            for (int i = 0; i < 4; i++)
                #pragma unroll
                for (int j = 0; j < 4; j++)
                    acc[i][j] += a[i] * b[j];
        }
        __syncthreads();
    }
    #pragma unroll
    for (int i = 0; i < 4; i++) {
        int row = m0 + ty * 4 + i;
        #pragma unroll
        for (int j = 0; j < 4; j++) {
            int col = n0 + tx * 4 + j;
            float v = acc[i][j] + bias[col];
            if (resid) v += resid[(size_t)row * NN + col];
            C[(size_t)row * NN + col] = v;
        }
    }
}

// ---------------- scores: S[h,n,m] = q·k/sqrt(32) + bias[n,m] ----------------
__global__ __launch_bounds__(256) void score_kernel() {
    __shared__ __align__(16) float Qs[32][68];
    __shared__ __align__(16) float Ks[32][68];
    int t = threadIdx.x;
    int h = blockIdx.z;
    int n0 = blockIdx.y * 64, m0 = blockIdx.x * 64;
    #pragma unroll
    for (int i = 0; i < 8; i++) {
        int idx = i * 256 + t;
        int r = idx >> 5, d = idx & 31;
        Qs[d][r] = g_qkv[(size_t)(n0 + r) * QKV + h * DH + d];
        Ks[d][r] = g_qkv[(size_t)(m0 + r) * QKV + 256 + h * DH + d];
    }
    __syncthreads();
    int tx = t & 15, ty = t >> 4;
    float acc[4][4] = {};
    #pragma unroll
    for (int d = 0; d < 32; d++) {
        float4 a = *(const float4*)&Qs[d][ty * 4];
        float4 b = *(const float4*)&Ks[d][tx * 4];
        float av[4] = {a.x, a.y, a.z, a.w};
        float bv[4] = {b.x, b.y, b.z, b.w};
        #pragma unroll
        for (int i = 0; i < 4; i++)
            #pragma unroll
            for (int j = 0; j < 4; j++)
                acc[i][j] += av[i] * bv[j];
    }
    const float sc = 0.17677669529663689f;  // 1/sqrt(32)
    #pragma unroll
    for (int i = 0; i < 4; i++) {
        int r = n0 + ty * 4 + i;
        float4 bi = *(const float4*)&g_bias[(size_t)r * N + m0 + tx * 4];
        float4 o;
        o.x = acc[i][0] * sc + bi.x; o.y = acc[i][1] * sc + bi.y;
        o.z = acc[i][2] * sc + bi.z; o.w = acc[i][3] * sc + bi.w;
        *(float4*)&g_S[((size_t)h * N + r) * N + m0 + tx * 4] = o;
    }
}

// ---------------- mean-shift iteration (no-max softmax). save: write P + sums ----------------
__global__ __launch_bounds__(256) void iter_kernel(const float* __restrict__ xin,
                                                   float* __restrict__ xout,
                                                   int save) {
    __shared__ __align__(16) float xsx[N];
    __shared__ __align__(16) float xsy[N];
    __shared__ __align__(16) float xsz[N];
    __shared__ float wred[H][3];
    int t = threadIdx.x;
    for (int i = t; i < N; i += 256) {
        xsx[i] = xin[i * 3];
        xsy[i] = xin[i * 3 + 1];
        xsz[i] = xin[i * 3 + 2];
    }
    __syncthreads();

    int h = t >> 5, lane = t & 31;
    int n = blockIdx.x;
    float xnx = xsx[n], xny = xsy[n], xnz = xsz[n];
    float* __restrict__ Srow = g_S + ((size_t)h * N + n) * N;

    float sm = 0.f, ax = 0.f, ay = 0.f, az = 0.f;
    for (int m4 = lane * 4; m4 < N; m4 += 128) {
        float4 s4 = *(const float4*)(Srow + m4);
        float4 bx4 = *(const float4*)&xsx[m4];
        float4 by4 = *(const float4*)&xsy[m4];
        float4 bz4 = *(const float4*)&xsz[m4];
        float sv[4] = {s4.x, s4.y, s4.z, s4.w};
        float bx[4] = {bx4.x, bx4.y, bx4.z, bx4.w};
        float by[4] = {by4.x, by4.y, by4.z, by4.w};
        float bz[4] = {bz4.x, bz4.y, bz4.z, bz4.w};
        float e[4];
        #pragma unroll
        for (int j = 0; j < 4; j++) {
            float dx = xnx - bx[j], dy = xny - by[j], dz = xnz - bz[j];
            float d2 = dx * dx + dy * dy + dz * dz;
            if (m4 + j == n) d2 = 1e-4f;  // SELF_DISTANCE^2
            float ee = __expf(sv[j] - 0.25f * d2);
            e[j] = ee;
            sm += ee;
            ax += ee * bx[j]; ay += ee * by[j]; az += ee * bz[j];
        }
        if (save) *(float4*)(Srow + m4) = make_float4(e[0], e[1], e[2], e[3]);
    }
    #pragma unroll
    for (int o = 16; o; o >>= 1) {
        sm += __shfl_xor_sync(0xffffffffu, sm, o);
        ax += __shfl_xor_sync(0xffffffffu, ax, o);
        ay += __shfl_xor_sync(0xffffffffu, ay, o);
        az += __shfl_xor_sync(0xffffffffu, az, o);
    }
    if (lane == 0) {
        if (save) g_sum[h * N + n] = sm;
        float inv = 1.f / sm;
        wred[h][0] = ax * inv; wred[h][1] = ay * inv; wred[h][2] = az * inv;
    }
    __syncthreads();
    if (t < 3) {
        float s = 0.f;
        #pragma unroll
        for (int hh = 0; hh < H; hh++) s += wred[hh][t];
        xout[n * 3 + t] = s * 0.125f;
    }
}

// ---------------- feat = (P @ V) * inv_sum ----------------
__global__ __launch_bounds__(256) void feat_kernel() {
    __shared__ __align__(16) float Ps[128][68];   // 68*4=272B row stride: 16B-aligned, conflict-free
    __shared__ __align__(16) float Vs[64][36];
    __shared__ float sms[128];
    int t = threadIdx.x;
    int h = blockIdx.y;
    int n0 = blockIdx.x * 128;

    if (t < 128) sms[t] = g_sum[h * N + n0 + t];

    int dg = t & 7, rg = t >> 3;
    int d4 = dg * 4, r0 = rg * 4;
    float acc[4][4] = {};

    for (int mb = 0; mb < N; mb += 64) {
        __syncthreads();
        // load P tile [128][64] as float4
        #pragma unroll
        for (int i = 0; i < 8; i++) {
            int idx = i * 256 + t;
            int r = idx >> 4, m4 = (idx & 15) * 4;
            *(float4*)&Ps[r][m4] =
                *(const float4*)&g_S[((size_t)h * N + n0 + r) * N + mb + m4];
        }
        // load V tile [64][32]
        #pragma unroll
        for (int i = 0; i < 8; i++) {
            int idx = i * 256 + t;
            int j = idx >> 5, d = idx & 31;
            Vs[j][d] = g_qkv[(size_t)(mb + j) * QKV + 512 + h * DH + d];
        }
        __syncthreads();
        #pragma unroll 2
        for (int j = 0; j < 64; j++) {
            float4 v = *(const float4*)&Vs[j][d4];
            #pragma unroll
            for (int i = 0; i < 4; i++) {
                float p = Ps[r0 + i][j];
                acc[i][0] += p * v.x;
                acc[i][1] += p * v.y;
                acc[i][2] += p * v.z;
                acc[i][3] += p * v.w;
            }
        }
    }
    #pragma unroll
    for (int i = 0; i < 4; i++) {
        int row = n0 + r0 + i;
        float inv = 1.f / sms[r0 + i];
        float4 o;
        o.x = acc[i][0] * inv; o.y = acc[i][1] * inv;
        o.z = acc[i][2] * inv; o.w = acc[i][3] * inv;
        *(float4*)&g_feat[(size_t)row * D + h * DH + d4] = o;
    }
}

// ---------------- launch ----------------
extern "C" void kernel_launch(void* const* d_in, const int* in_sizes, int n_in,
                              void* d_out, int out_size) {
    const float* x   = (const float*)d_in[0];
    const float* xyz = (const float*)d_in[1];
    const float* dy  = (const float*)d_in[2];
    const void*  dm  = d_in[3];
    const void*  bim = d_in[4];
    const float* Wq = (const float*)d_in[5];
    const float* bq = (const float*)d_in[6];
    const float* Wk = (const float*)d_in[7];
    const float* bk = (const float*)d_in[8];
    const float* Wv = (const float*)d_in[9];
    const float* bv = (const float*)d_in[10];
    const float* Wo = (const float*)d_in[11];
    const float* bo = (const float*)d_in[12];
    float* out = (float*)d_out;

    float *qkv, *wqkv, *bqkv, *feat, *xb;
    cudaGetSymbolAddress((void**)&qkv, g_qkv);
    cudaGetSymbolAddress((void**)&wqkv, g_Wqkv);
    cudaGetSymbolAddress((void**)&bqkv, g_bqkv);
    cudaGetSymbolAddress((void**)&feat, g_feat);
    cudaGetSymbolAddress((void**)&xb, g_xyz);
    float* xbuf0 = xb;
    float* xbuf1 = xb + N * 3;

    float* xyz_dst = xbuf0;
    float* out_dst = out;
    if (out_size == N * 3 + N * D) { xyz_dst = out; out_dst = out + N * 3; }
    else if (out_size == N * D)    { out_dst = out; }
    else if (out_size == N * 3)    { xyz_dst = out; out_dst = feat; }

    detect_kernel<<<1, 256>>>((const unsigned char*)bim);
    bias_kernel<<<N, 256>>>(dy, dm, bim);
    pack_kernel<<<256, 256>>>(Wq, Wk, Wv, bq, bk, bv);

    gemm64<<<dim3(12, 48), 256>>>(x, wqkv, bqkv, nullptr, qkv, N, D, QKV);

    score_kernel<<<dim3(48, 48, 8), 256>>>();

    iter_kernel<<<N, 256>>>(xyz, xbuf0, 0);
    iter_kernel<<<N, 256>>>(xbuf0, xbuf1, 0);
    iter_kernel<<<N, 256>>>(xbuf1, xyz_dst, 1);  // writes P into g_S + row sums

    feat_kernel<<<dim3(24, 8), 256>>>();

    gemm64<<<dim3(4, 48), 256>>>(feat, Wo, bo, x, out_dst, N, D, D);
}

// round 8
// speedup vs baseline: 2.5603x; 1.1297x over previous
#include <cuda_runtime.h>
#include <math.h>
#include <stdint.h>

#define N 3072
#define D 256
#define H 8
#define DH 32
#define QKV 768
#define Z 3
#define MR 1024   // m-range per z-slice (3*1024 = 3072)

// ---------------- scratch ----------------
__device__ float g_qkv[N * QKV];
__device__ float g_Wqkv[D * QKV];
__device__ float g_bqkv[QKV];
__device__ float g_feat[N * D];
__device__ float g_S[8ull * 3072ull * 3072ull];   // logits (score + bias)
__device__ float g_bias[3072ull * 3072ull];
__device__ float g_xyz[2][N * 3];
__device__ float g_pse[Z][H * N];
__device__ float g_psx[Z][H * N];
__device__ float g_psy[Z][H * N];
__device__ float g_psz[Z][H * N];
__device__ float g_featP[Z][N * D];
__device__ int   g_mask_mode;

// ---------------- mask dtype detection ----------------
__global__ void detect_kernel(const unsigned char* __restrict__ p) {
    __shared__ int c1, c3;
    int t = threadIdx.x;
    if (t == 0) { c1 = 0; c3 = 0; }
    __syncthreads();
    int l1 = 0, l3 = 0;
    for (int i = t; i < 16384; i += 256) {
        l1 += (p[i * 4 + 1] != 0);
        l3 += (p[i * 4 + 3] != 0);
    }
    atomicAdd(&c1, l1);
    atomicAdd(&c3, l3);
    __syncthreads();
    if (t == 0) g_mask_mode = (c3 == 0) ? 0 : ((c1 == 0) ? 1 : 2);
}

// ---------------- bias: B[n,m] = valid ? -delta_y : -1e30 ----------------
__global__ __launch_bounds__(256) void bias_kernel(const float* __restrict__ dy,
                                                   const void* __restrict__ dm,
                                                   const void* __restrict__ bim) {
    int n = blockIdx.x;
    int mode = g_mask_mode;
    size_t row = (size_t)n * N;
    for (int m = threadIdx.x; m < N; m += 256) {
        bool a, b;
        if (mode == 0) {
            a = ((const int*)dm)[row + m] != 0;
            b = ((const int*)bim)[row + m] != 0;
        } else if (mode == 1) {
            a = ((const float*)dm)[row + m] != 0.0f;
            b = ((const float*)bim)[row + m] != 0.0f;
        } else {
            a = ((const unsigned char*)dm)[row + m] != 0;
            b = ((const unsigned char*)bim)[row + m] != 0;
        }
        bool valid = (a && b) || (m == n);
        g_bias[row + m] = valid ? -dy[row + m] : -1e30f;
    }
}

// ---------------- pack [Wq|Wk|Wv] and biases ----------------
__global__ __launch_bounds__(256) void pack_kernel(const float* __restrict__ Wq,
                                                   const float* __restrict__ Wk,
                                                   const float* __restrict__ Wv,
                                                   const float* __restrict__ bq,
                                                   const float* __restrict__ bk,
                                                   const float* __restrict__ bv) {
    int idx = blockIdx.x * 256 + threadIdx.x;
    int row = idx >> 8, col = idx & 255;
    g_Wqkv[row * QKV + col]       = Wq[idx];
    g_Wqkv[row * QKV + 256 + col] = Wk[idx];
    g_Wqkv[row * QKV + 512 + col] = Wv[idx];
    if (idx < 256) {
        g_bqkv[idx]       = bq[idx];
        g_bqkv[256 + idx] = bk[idx];
        g_bqkv[512 + idx] = bv[idx];
    }
}

// ---------------- generic tiled GEMM ----------------
__global__ __launch_bounds__(256) void gemm64(const float* __restrict__ A,
                                              const float* __restrict__ W,
                                              const float* __restrict__ bias,
                                              const float* __restrict__ resid,
                                              float* __restrict__ C,
                                              int M, int K, int NN) {
    __shared__ float As[16][65];
    __shared__ float Ws[16][65];
    int t = threadIdx.x;
    int tx = t & 15, ty = t >> 4;
    int n0 = blockIdx.x * 64, m0 = blockIdx.y * 64;
    float acc[4][4] = {};
    for (int kt = 0; kt < K; kt += 16) {
        #pragma unroll
        for (int i = 0; i < 4; i++) {
            int idx = i * 256 + t;
            int r = idx >> 4, kk = idx & 15;
            As[kk][r] = A[(size_t)(m0 + r) * K + kt + kk];
        }
        #pragma unroll
        for (int i = 0; i < 4; i++) {
            int idx = i * 256 + t;
            int kk = idx >> 6, j = idx & 63;
            Ws[kk][j] = W[(size_t)(kt + kk) * NN + n0 + j];
        }
        __syncthreads();
        #pragma unroll
        for (int kk = 0; kk < 16; kk++) {
            float a[4], b[4];
            #pragma unroll
            for (int i = 0; i < 4; i++) a[i] = As[kk][ty * 4 + i];
            #pragma unroll
            for (int j = 0; j < 4; j++) b[j] = Ws[kk][tx * 4 + j];
            #pragma unroll
            for (int i = 0; i < 4; i++)
                #pragma unroll
                for (int j = 0; j < 4; j++)
                    acc[i][j] += a[i] * b[j];
        }
        __syncthreads();
    }
    #pragma unroll
    for (int i = 0; i < 4; i++) {
        int row = m0 + ty * 4 + i;
        #pragma unroll
        for (int j = 0; j < 4; j++) {
            int col = n0 + tx * 4 + j;
            float v = acc[i][j] + bias[col];
            if (resid) v += resid[(size_t)row * NN + col];
            C[(size_t)row * NN + col] = v;
        }
    }
}

// ---------------- fused score + iter1: write logits, accumulate iter1 sums ----------------
// 64-row n-tile per block (grid.x = 48), 64-col m-steps over a 1024-wide z-slice.
__global__ __launch_bounds__(256) void score_iter1_kernel(const float* __restrict__ xin) {
    __shared__ __align__(16) float Qs[32][68];
    __shared__ __align__(16) float Ks[32][68];
    __shared__ float xcx[64], xcy[64], xcz[64];
    int t = threadIdx.x;
    int h = blockIdx.y, z = blockIdx.z;
    int n0 = blockIdx.x * 64;
    int tx = t & 15, ty = t >> 4;

    #pragma unroll
    for (int i = 0; i < 8; i++) {
        int idx = i * 256 + t;
        int r = idx >> 5, d = idx & 31;
        Qs[d][r] = g_qkv[(size_t)(n0 + r) * QKV + h * DH + d];
    }
    float xrx[4], xry[4], xrz[4];
    #pragma unroll
    for (int i = 0; i < 4; i++) {
        int r = n0 + ty * 4 + i;
        xrx[i] = xin[r * 3]; xry[i] = xin[r * 3 + 1]; xrz[i] = xin[r * 3 + 2];
    }
    float se[4] = {}, sx[4] = {}, sy[4] = {}, sz[4] = {};
    const float sc = 0.17677669529663689f;  // 1/sqrt(32)

    for (int mb = 0; mb < MR; mb += 64) {
        int m0 = z * MR + mb;
        __syncthreads();
        #pragma unroll
        for (int i = 0; i < 8; i++) {
            int idx = i * 256 + t;
            int j = idx >> 5, d = idx & 31;
            Ks[d][j] = g_qkv[(size_t)(m0 + j) * QKV + 256 + h * DH + d];
        }
        if (t < 64)       xcx[t]       = xin[(m0 + t) * 3];
        else if (t < 128) xcy[t - 64]  = xin[(m0 + t - 64) * 3 + 1];
        else if (t < 192) xcz[t - 128] = xin[(m0 + t - 128) * 3 + 2];
        __syncthreads();

        float acc[4][4] = {};
        #pragma unroll
        for (int d = 0; d < 32; d++) {
            float4 a = *(const float4*)&Qs[d][ty * 4];
            float4 b = *(const float4*)&Ks[d][tx * 4];
            float av[4] = {a.x, a.y, a.z, a.w};
            float bv[4] = {b.x, b.y, b.z, b.w};
            #pragma unroll
            for (int i = 0; i < 4; i++)
                #pragma unroll
                for (int j = 0; j < 4; j++)
                    acc[i][j] += av[i] * bv[j];
        }
        float cx[4], cy[4], cz[4];
        #pragma unroll
        for (int j = 0; j < 4; j++) {
            int jj = tx * 4 + j;
            cx[j] = xcx[jj]; cy[j] = xcy[jj]; cz[j] = xcz[jj];
        }
        #pragma unroll
        for (int i = 0; i < 4; i++) {
            int r = n0 + ty * 4 + i;
            float4 bi = *(const float4*)&g_bias[(size_t)r * N + m0 + tx * 4];
            float bb[4] = {bi.x, bi.y, bi.z, bi.w};
            float4 so;
            float* sop = (float*)&so;
            #pragma unroll
            for (int j = 0; j < 4; j++) {
                int m = m0 + tx * 4 + j;
                float dx = xrx[i] - cx[j], dy = xry[i] - cy[j], dz = xrz[i] - cz[j];
                float d2 = dx * dx + dy * dy + dz * dz;
                if (m == r) d2 = 1e-4f;
                float lg = acc[i][j] * sc + bb[j];
                sop[j] = lg;
                float e = __expf(lg - 0.25f * d2);
                se[i] += e;
                sx[i] += e * cx[j]; sy[i] += e * cy[j]; sz[i] += e * cz[j];
            }
            *(float4*)&g_S[((size_t)h * N + r) * N + m0 + tx * 4] = so;
        }
    }
    // reduce across the 16 tx lanes (stays inside each half-warp)
    #pragma unroll
    for (int i = 0; i < 4; i++) {
        #pragma unroll
        for (int o = 8; o; o >>= 1) {
            se[i] += __shfl_xor_sync(0xffffffffu, se[i], o);
            sx[i] += __shfl_xor_sync(0xffffffffu, sx[i], o);
            sy[i] += __shfl_xor_sync(0xffffffffu, sy[i], o);
            sz[i] += __shfl_xor_sync(0xffffffffu, sz[i], o);
        }
        if (tx == 0) {
            int r = n0 + ty * 4 + i;
            g_pse[z][h * N + r] = se[i];
            g_psx[z][h * N + r] = sx[i];
            g_psy[z][h * N + r] = sy[i];
            g_psz[z][h * N + r] = sz[i];
        }
    }
}

// ---------------- combine partial xyz sums -> new xyz ----------------
__global__ void combine_xyz_kernel(float* __restrict__ xout) {
    int n = blockIdx.x * 256 + threadIdx.x;
    float ox = 0.f, oy = 0.f, oz = 0.f;
    #pragma unroll
    for (int h = 0; h < H; h++) {
        int idx = h * N + n;
        float se = g_pse[0][idx] + g_pse[1][idx] + g_pse[2][idx];
        float inv = 1.f / se;
        ox += (g_psx[0][idx] + g_psx[1][idx] + g_psx[2][idx]) * inv;
        oy += (g_psy[0][idx] + g_psy[1][idx] + g_psy[2][idx]) * inv;
        oz += (g_psz[0][idx] + g_psz[1][idx] + g_psz[2][idx]) * inv;
    }
    xout[n * 3]     = ox * 0.125f;
    xout[n * 3 + 1] = oy * 0.125f;
    xout[n * 3 + 2] = oz * 0.125f;
}

// ---------------- iter2: standard streaming softmax mean-shift ----------------
__global__ __launch_bounds__(256) void iter_kernel(const float* __restrict__ xin,
                                                   float* __restrict__ xout) {
    __shared__ __align__(16) float xsx[N];
    __shared__ __align__(16) float xsy[N];
    __shared__ __align__(16) float xsz[N];
    __shared__ float wred[H][3];
    int t = threadIdx.x;
    for (int i = t; i < N; i += 256) {
        xsx[i] = xin[i * 3];
        xsy[i] = xin[i * 3 + 1];
        xsz[i] = xin[i * 3 + 2];
    }
    __syncthreads();

    int h = t >> 5, lane = t & 31;
    int n = blockIdx.x;
    float xnx = xsx[n], xny = xsy[n], xnz = xsz[n];
    const float* __restrict__ Srow = g_S + ((size_t)h * N + n) * N;

    float sm = 0.f, ax = 0.f, ay = 0.f, az = 0.f;
    for (int m4 = lane * 4; m4 < N; m4 += 128) {
        float4 s4 = *(const float4*)(Srow + m4);
        float4 bx4 = *(const float4*)&xsx[m4];
        float4 by4 = *(const float4*)&xsy[m4];
        float4 bz4 = *(const float4*)&xsz[m4];
        float sv[4] = {s4.x, s4.y, s4.z, s4.w};
        float bx[4] = {bx4.x, bx4.y, bx4.z, bx4.w};
        float by[4] = {by4.x, by4.y, by4.z, by4.w};
        float bz[4] = {bz4.x, bz4.y, bz4.z, bz4.w};
        #pragma unroll
        for (int j = 0; j < 4; j++) {
            float dx = xnx - bx[j], dy = xny - by[j], dz = xnz - bz[j];
            float d2 = dx * dx + dy * dy + dz * dz;
            if (m4 + j == n) d2 = 1e-4f;
            float ee = __expf(sv[j] - 0.25f * d2);
            sm += ee;
            ax += ee * bx[j]; ay += ee * by[j]; az += ee * bz[j];
        }
    }
    #pragma unroll
    for (int o = 16; o; o >>= 1) {
        sm += __shfl_xor_sync(0xffffffffu, sm, o);
        ax += __shfl_xor_sync(0xffffffffu, ax, o);
        ay += __shfl_xor_sync(0xffffffffu, ay, o);
        az += __shfl_xor_sync(0xffffffffu, az, o);
    }
    if (lane == 0) {
        float inv = 1.f / sm;
        wred[h][0] = ax * inv; wred[h][1] = ay * inv; wred[h][2] = az * inv;
    }
    __syncthreads();
    if (t < 3) {
        float s = 0.f;
        #pragma unroll
        for (int hh = 0; hh < H; hh++) s += wred[hh][t];
        xout[n * 3 + t] = s * 0.125f;
    }
}

// ---------------- fused iter3 + feat: P never materialized ----------------
__global__ __launch_bounds__(256) void iter3_feat_kernel(const float* __restrict__ xin) {
    __shared__ __align__(16) float Ps[128][68];
    __shared__ __align__(16) float Vs[64][36];
    __shared__ float xcx[64], xcy[64], xcz[64];
    int t = threadIdx.x;
    int h = blockIdx.y, z = blockIdx.z;
    int n0 = blockIdx.x * 128;

    // e-phase mapping: thread owns row er, half j0
    int er = t >> 1, j0 = (t & 1) * 32;
    float xr0 = xin[(n0 + er) * 3];
    float xr1 = xin[(n0 + er) * 3 + 1];
    float xr2 = xin[(n0 + er) * 3 + 2];
    // gemm mapping
    int dg = t & 7, rg = t >> 3;
    int d4 = dg * 4, r0 = rg * 4;
    float acc[4][4] = {};
    float se = 0.f, sx = 0.f, sy = 0.f, sz = 0.f;

    for (int mb = 0; mb < MR; mb += 64) {
        int m0 = z * MR + mb;
        __syncthreads();  // previous gemm done with Ps/Vs
        #pragma unroll
        for (int i = 0; i < 8; i++) {
            int idx = i * 256 + t;
            int j = idx >> 5, d = idx & 31;
            Vs[j][d] = g_qkv[(size_t)(m0 + j) * QKV + 512 + h * DH + d];
        }
        if (t < 64)       xcx[t]       = xin[(m0 + t) * 3];
        else if (t < 128) xcy[t - 64]  = xin[(m0 + t - 64) * 3 + 1];
        else if (t < 192) xcz[t - 128] = xin[(m0 + t - 128) * 3 + 2];
        __syncthreads();  // xc ready for e-phase
        #pragma unroll
        for (int jj = 0; jj < 32; jj += 4) {
            float4 s4 = *(const float4*)&g_S[((size_t)h * N + n0 + er) * N + m0 + j0 + jj];
            float sv[4] = {s4.x, s4.y, s4.z, s4.w};
            float4 eo;
            float* eop = (float*)&eo;
            #pragma unroll
            for (int c = 0; c < 4; c++) {
                int j = j0 + jj + c;
                float cxv = xcx[j], cyv = xcy[j], czv = xcz[j];
                float dx = xr0 - cxv, dy = xr1 - cyv, dz = xr2 - czv;
                float d2 = dx * dx + dy * dy + dz * dz;
                if (m0 + j == n0 + er) d2 = 1e-4f;
                float e = __expf(sv[c] - 0.25f * d2);
                eop[c] = e;
                se += e;
                sx += e * cxv; sy += e * cyv; sz += e * czv;
            }
            *(float4*)&Ps[er][j0 + jj] = eo;
        }
        __syncthreads();  // Ps ready for gemm
        #pragma unroll 2
        for (int j = 0; j < 64; j++) {
            float4 v = *(const float4*)&Vs[j][d4];
            #pragma unroll
            for (int i = 0; i < 4; i++) {
                float p = Ps[r0 + i][j];
                acc[i][0] += p * v.x;
                acc[i][1] += p * v.y;
                acc[i][2] += p * v.z;
                acc[i][3] += p * v.w;
            }
        }
    }
    // pair-combine sums (threads t, t^1 share row er)
    se += __shfl_xor_sync(0xffffffffu, se, 1);
    sx += __shfl_xor_sync(0xffffffffu, sx, 1);
    sy += __shfl_xor_sync(0xffffffffu, sy, 1);
    sz += __shfl_xor_sync(0xffffffffu, sz, 1);
    if (!(t & 1)) {
        g_pse[z][h * N + n0 + er] = se;
        g_psx[z][h * N + n0 + er] = sx;
        g_psy[z][h * N + n0 + er] = sy;
        g_psz[z][h * N + n0 + er] = sz;
    }
    // partial (unnormalized) feat
    #pragma unroll
    for (int i = 0; i < 4; i++) {
        float4 o;
        o.x = acc[i][0]; o.y = acc[i][1]; o.z = acc[i][2]; o.w = acc[i][3];
        *(float4*)&g_featP[z][(size_t)(n0 + r0 + i) * D + h * DH + d4] = o;
    }
}

// ---------------- combine feat partials, normalize ----------------
__global__ __launch_bounds__(256) void combine_feat_kernel() {
    int n = blockIdx.x;
    int c = threadIdx.x;
    int h = c >> 5;
    int idx = h * N + n;
    float inv = 1.f / (g_pse[0][idx] + g_pse[1][idx] + g_pse[2][idx]);
    size_t o = (size_t)n * D + c;
    g_feat[o] = (g_featP[0][o] + g_featP[1][o] + g_featP[2][o]) * inv;
}

// ---------------- launch ----------------
extern "C" void kernel_launch(void* const* d_in, const int* in_sizes, int n_in,
                              void* d_out, int out_size) {
    const float* x   = (const float*)d_in[0];
    const float* xyz = (const float*)d_in[1];
    const float* dy  = (const float*)d_in[2];
    const void*  dm  = d_in[3];
    const void*  bim = d_in[4];
    const float* Wq = (const float*)d_in[5];
    const float* bq = (const float*)d_in[6];
    const float* Wk = (const float*)d_in[7];
    const float* bk = (const float*)d_in[8];
    const float* Wv = (const float*)d_in[9];
    const float* bv = (const float*)d_in[10];
    const float* Wo = (const float*)d_in[11];
    const float* bo = (const float*)d_in[12];
    float* out = (float*)d_out;

    float *qkv, *wqkv, *bqkv, *feat, *xb;
    cudaGetSymbolAddress((void**)&qkv, g_qkv);
    cudaGetSymbolAddress((void**)&wqkv, g_Wqkv);
    cudaGetSymbolAddress((void**)&bqkv, g_bqkv);
    cudaGetSymbolAddress((void**)&feat, g_feat);
    cudaGetSymbolAddress((void**)&xb, g_xyz);
    float* xbuf0 = xb;
    float* xbuf1 = xb + N * 3;

    float* xyz_dst = xbuf0;
    float* out_dst = out;
    if (out_size == N * 3 + N * D) { xyz_dst = out; out_dst = out + N * 3; }
    else if (out_size == N * D)    { out_dst = out; }
    else if (out_size == N * 3)    { xyz_dst = out; out_dst = qkv; }

    detect_kernel<<<1, 256>>>((const unsigned char*)bim);
    bias_kernel<<<N, 256>>>(dy, dm, bim);
    pack_kernel<<<256, 256>>>(Wq, Wk, Wv, bq, bk, bv);

    gemm64<<<dim3(12, 48), 256>>>(x, wqkv, bqkv, nullptr, qkv, N, D, QKV);

    // fused score + iter1 (uses original xyz); 48 x-tiles of 64 rows
    score_iter1_kernel<<<dim3(48, 8, Z), 256>>>(xyz);
    combine_xyz_kernel<<<12, 256>>>(xbuf0);           // -> xyz1

    iter_kernel<<<N, 256>>>(xbuf0, xbuf1);            // -> xyz2

    // fused iter3 + feat (uses xyz2)
    iter3_feat_kernel<<<dim3(24, 8, Z), 256>>>(xbuf1);
    combine_xyz_kernel<<<12, 256>>>(xyz_dst);         // -> xyz3
    combine_feat_kernel<<<N, 256>>>();                // -> g_feat

    gemm64<<<dim3(4, 48), 256>>>(feat, Wo, bo, x, out_dst, N, D, D);
}

// round 9
// speedup vs baseline: 2.6882x; 1.0500x over previous
#include <cuda_runtime.h>
#include <math.h>
#include <stdint.h>

#define N 3072
#define D 256
#define H 8
#define DH 32
#define QKV 768
#define Z 3
#define MR 1024   // m-range per z-slice (3*1024 = 3072)

typedef unsigned long long u64;

// ---- packed f32x2 helpers (sm_103a) ----
__device__ __forceinline__ u64 bcast2(float v) {
    u64 r;
    asm("mov.b64 %0, {%1, %1};" : "=l"(r) : "f"(v));
    return r;
}
__device__ __forceinline__ void ffma2(u64& d, u64 a, u64 b) {
    asm("fma.rn.f32x2 %0, %1, %2, %3;" : "=l"(d) : "l"(a), "l"(b), "l"(d));
}
__device__ __forceinline__ float2 unpack2(u64 v) {
    float2 f;
    asm("mov.b64 {%0, %1}, %2;" : "=f"(f.x), "=f"(f.y) : "l"(v));
    return f;
}

// ---------------- scratch ----------------
__device__ float g_qkv[N * QKV];
__device__ float g_Wqkv[D * QKV];
__device__ float g_bqkv[QKV];
__device__ float g_feat[N * D];
__device__ float g_S[8ull * 3072ull * 3072ull];   // logits (score + bias)
__device__ float g_bias[3072ull * 3072ull];
__device__ float g_xyz[2][N * 3];
__device__ float g_pse[Z][H * N];
__device__ float g_psx[Z][H * N];
__device__ float g_psy[Z][H * N];
__device__ float g_psz[Z][H * N];
__device__ float g_featP[Z][N * D];
__device__ int   g_mask_mode;

// ---------------- mask dtype detection ----------------
__global__ void detect_kernel(const unsigned char* __restrict__ p) {
    __shared__ int c1, c3;
    int t = threadIdx.x;
    if (t == 0) { c1 = 0; c3 = 0; }
    __syncthreads();
    int l1 = 0, l3 = 0;
    for (int i = t; i < 16384; i += 256) {
        l1 += (p[i * 4 + 1] != 0);
        l3 += (p[i * 4 + 3] != 0);
    }
    atomicAdd(&c1, l1);
    atomicAdd(&c3, l3);
    __syncthreads();
    if (t == 0) g_mask_mode = (c3 == 0) ? 0 : ((c1 == 0) ? 1 : 2);
}

// ---------------- bias: B[n,m] = valid ? -delta_y : -1e30 ----------------
__global__ __launch_bounds__(256) void bias_kernel(const float* __restrict__ dy,
                                                   const void* __restrict__ dm,
                                                   const void* __restrict__ bim) {
    int n = blockIdx.x;
    int mode = g_mask_mode;
    size_t row = (size_t)n * N;
    for (int m = threadIdx.x; m < N; m += 256) {
        bool a, b;
        if (mode == 0) {
            a = ((const int*)dm)[row + m] != 0;
            b = ((const int*)bim)[row + m] != 0;
        } else if (mode == 1) {
            a = ((const float*)dm)[row + m] != 0.0f;
            b = ((const float*)bim)[row + m] != 0.0f;
        } else {
            a = ((const unsigned char*)dm)[row + m] != 0;
            b = ((const unsigned char*)bim)[row + m] != 0;
        }
        bool valid = (a && b) || (m == n);
        g_bias[row + m] = valid ? -dy[row + m] : -1e30f;
    }
}

// ---------------- pack [Wq|Wk|Wv] and biases ----------------
__global__ __launch_bounds__(256) void pack_kernel(const float* __restrict__ Wq,
                                                   const float* __restrict__ Wk,
                                                   const float* __restrict__ Wv,
                                                   const float* __restrict__ bq,
                                                   const float* __restrict__ bk,
                                                   const float* __restrict__ bv) {
    int idx = blockIdx.x * 256 + threadIdx.x;
    int row = idx >> 8, col = idx & 255;
    g_Wqkv[row * QKV + col]       = Wq[idx];
    g_Wqkv[row * QKV + 256 + col] = Wk[idx];
    g_Wqkv[row * QKV + 512 + col] = Wv[idx];
    if (idx < 256) {
        g_bqkv[idx]       = bq[idx];
        g_bqkv[256 + idx] = bk[idx];
        g_bqkv[512 + idx] = bv[idx];
    }
}

// ---------------- generic tiled GEMM (FFMA2 inner) ----------------
__global__ __launch_bounds__(256) void gemm64(const float* __restrict__ A,
                                              const float* __restrict__ W,
                                              const float* __restrict__ bias,
                                              const float* __restrict__ resid,
                                              float* __restrict__ C,
                                              int M, int K, int NN) {
    __shared__ __align__(16) float As[16][68];
    __shared__ __align__(16) float Ws[16][68];
    int t = threadIdx.x;
    int tx = t & 15, ty = t >> 4;
    int n0 = blockIdx.x * 64, m0 = blockIdx.y * 64;
    u64 acc2[2][4] = {};
    for (int kt = 0; kt < K; kt += 16) {
        #pragma unroll
        for (int i = 0; i < 4; i++) {
            int idx = i * 256 + t;
            int r = idx >> 4, kk = idx & 15;
            As[kk][r] = A[(size_t)(m0 + r) * K + kt + kk];
        }
        #pragma unroll
        for (int i = 0; i < 4; i++) {
            int idx = i * 256 + t;
            int kk = idx >> 6, j = idx & 63;
            Ws[kk][j] = W[(size_t)(kt + kk) * NN + n0 + j];
        }
        __syncthreads();
        #pragma unroll
        for (int kk = 0; kk < 16; kk++) {
            ulonglong2 av = *(const ulonglong2*)&As[kk][ty * 4];  // rows (ty*4..+3) packed
            float4 b = *(const float4*)&Ws[kk][tx * 4];
            u64 b0 = bcast2(b.x), b1 = bcast2(b.y), b2 = bcast2(b.z), b3 = bcast2(b.w);
            ffma2(acc2[0][0], av.x, b0); ffma2(acc2[0][1], av.x, b1);
            ffma2(acc2[0][2], av.x, b2); ffma2(acc2[0][3], av.x, b3);
            ffma2(acc2[1][0], av.y, b0); ffma2(acc2[1][1], av.y, b1);
            ffma2(acc2[1][2], av.y, b2); ffma2(acc2[1][3], av.y, b3);
        }
        __syncthreads();
    }
    float acc[4][4];
    #pragma unroll
    for (int j = 0; j < 4; j++) {
        float2 p0 = unpack2(acc2[0][j]);
        float2 p1 = unpack2(acc2[1][j]);
        acc[0][j] = p0.x; acc[1][j] = p0.y;
        acc[2][j] = p1.x; acc[3][j] = p1.y;
    }
    #pragma unroll
    for (int i = 0; i < 4; i++) {
        int row = m0 + ty * 4 + i;
        #pragma unroll
        for (int j = 0; j < 4; j++) {
            int col = n0 + tx * 4 + j;
            float v = acc[i][j] + bias[col];
            if (resid) v += resid[(size_t)row * NN + col];
            C[(size_t)row * NN + col] = v;
        }
    }
}

// ---------------- fused score + iter1 (FFMA2 inner) ----------------
__global__ __launch_bounds__(256) void score_iter1_kernel(const float* __restrict__ xin) {
    __shared__ __align__(16) float Qs[32][68];
    __shared__ __align__(16) float Ks[32][68];
    __shared__ float xcx[64], xcy[64], xcz[64];
    int t = threadIdx.x;
    int h = blockIdx.y, z = blockIdx.z;
    int n0 = blockIdx.x * 64;
    int tx = t & 15, ty = t >> 4;

    #pragma unroll
    for (int i = 0; i < 8; i++) {
        int idx = i * 256 + t;
        int r = idx >> 5, d = idx & 31;
        Qs[d][r] = g_qkv[(size_t)(n0 + r) * QKV + h * DH + d];
    }
    float xrx[4], xry[4], xrz[4];
    #pragma unroll
    for (int i = 0; i < 4; i++) {
        int r = n0 + ty * 4 + i;
        xrx[i] = xin[r * 3]; xry[i] = xin[r * 3 + 1]; xrz[i] = xin[r * 3 + 2];
    }
    float se[4] = {}, sx[4] = {}, sy[4] = {}, sz[4] = {};
    const float sc = 0.17677669529663689f;  // 1/sqrt(32)

    for (int mb = 0; mb < MR; mb += 64) {
        int m0 = z * MR + mb;
        __syncthreads();
        #pragma unroll
        for (int i = 0; i < 8; i++) {
            int idx = i * 256 + t;
            int j = idx >> 5, d = idx & 31;
            Ks[d][j] = g_qkv[(size_t)(m0 + j) * QKV + 256 + h * DH + d];
        }
        if (t < 64)       xcx[t]       = xin[(m0 + t) * 3];
        else if (t < 128) xcy[t - 64]  = xin[(m0 + t - 64) * 3 + 1];
        else if (t < 192) xcz[t - 128] = xin[(m0 + t - 128) * 3 + 2];
        __syncthreads();

        u64 acc2[2][4] = {};
        #pragma unroll
        for (int d = 0; d < 32; d++) {
            ulonglong2 av = *(const ulonglong2*)&Qs[d][ty * 4];  // rows packed
            float4 b = *(const float4*)&Ks[d][tx * 4];
            u64 b0 = bcast2(b.x), b1 = bcast2(b.y), b2 = bcast2(b.z), b3 = bcast2(b.w);
            ffma2(acc2[0][0], av.x, b0); ffma2(acc2[0][1], av.x, b1);
            ffma2(acc2[0][2], av.x, b2); ffma2(acc2[0][3], av.x, b3);
            ffma2(acc2[1][0], av.y, b0); ffma2(acc2[1][1], av.y, b1);
            ffma2(acc2[1][2], av.y, b2); ffma2(acc2[1][3], av.y, b3);
        }
        float acc[4][4];
        #pragma unroll
        for (int j = 0; j < 4; j++) {
            float2 p0 = unpack2(acc2[0][j]);
            float2 p1 = unpack2(acc2[1][j]);
            acc[0][j] = p0.x; acc[1][j] = p0.y;
            acc[2][j] = p1.x; acc[3][j] = p1.y;
        }
        float cx[4], cy[4], cz[4];
        #pragma unroll
        for (int j = 0; j < 4; j++) {
            int jj = tx * 4 + j;
            cx[j] = xcx[jj]; cy[j] = xcy[jj]; cz[j] = xcz[jj];
        }
        #pragma unroll
        for (int i = 0; i < 4; i++) {
            int r = n0 + ty * 4 + i;
            float4 bi = *(const float4*)&g_bias[(size_t)r * N + m0 + tx * 4];
            float bb[4] = {bi.x, bi.y, bi.z, bi.w};
            float4 so;
            float* sop = (float*)&so;
            #pragma unroll
            for (int j = 0; j < 4; j++) {
                int m = m0 + tx * 4 + j;
                float dx = xrx[i] - cx[j], dy = xry[i] - cy[j], dz = xrz[i] - cz[j];
                float d2 = dx * dx + dy * dy + dz * dz;
                if (m == r) d2 = 1e-4f;
                float lg = acc[i][j] * sc + bb[j];
                sop[j] = lg;
                float e = __expf(lg - 0.25f * d2);
                se[i] += e;
                sx[i] += e * cx[j]; sy[i] += e * cy[j]; sz[i] += e * cz[j];
            }
            *(float4*)&g_S[((size_t)h * N + r) * N + m0 + tx * 4] = so;
        }
    }
    #pragma unroll
    for (int i = 0; i < 4; i++) {
        #pragma unroll
        for (int o = 8; o; o >>= 1) {
            se[i] += __shfl_xor_sync(0xffffffffu, se[i], o);
            sx[i] += __shfl_xor_sync(0xffffffffu, sx[i], o);
            sy[i] += __shfl_xor_sync(0xffffffffu, sy[i], o);
            sz[i] += __shfl_xor_sync(0xffffffffu, sz[i], o);
        }
        if (tx == 0) {
            int r = n0 + ty * 4 + i;
            g_pse[z][h * N + r] = se[i];
            g_psx[z][h * N + r] = sx[i];
            g_psy[z][h * N + r] = sy[i];
            g_psz[z][h * N + r] = sz[i];
        }
    }
}

// ---------------- combine partial xyz sums -> new xyz ----------------
__global__ void combine_xyz_kernel(float* __restrict__ xout) {
    int n = blockIdx.x * 256 + threadIdx.x;
    float ox = 0.f, oy = 0.f, oz = 0.f;
    #pragma unroll
    for (int h = 0; h < H; h++) {
        int idx = h * N + n;
        float se = g_pse[0][idx] + g_pse[1][idx] + g_pse[2][idx];
        float inv = 1.f / se;
        ox += (g_psx[0][idx] + g_psx[1][idx] + g_psx[2][idx]) * inv;
        oy += (g_psy[0][idx] + g_psy[1][idx] + g_psy[2][idx]) * inv;
        oz += (g_psz[0][idx] + g_psz[1][idx] + g_psz[2][idx]) * inv;
    }
    xout[n * 3]     = ox * 0.125f;
    xout[n * 3 + 1] = oy * 0.125f;
    xout[n * 3 + 2] = oz * 0.125f;
}

// ---------------- iter2: streaming softmax mean-shift ----------------
__global__ __launch_bounds__(256) void iter_kernel(const float* __restrict__ xin,
                                                   float* __restrict__ xout) {
    __shared__ __align__(16) float xsx[N];
    __shared__ __align__(16) float xsy[N];
    __shared__ __align__(16) float xsz[N];
    __shared__ float wred[H][3];
    int t = threadIdx.x;
    for (int i = t; i < N; i += 256) {
        xsx[i] = xin[i * 3];
        xsy[i] = xin[i * 3 + 1];
        xsz[i] = xin[i * 3 + 2];
    }
    __syncthreads();

    int h = t >> 5, lane = t & 31;
    int n = blockIdx.x;
    float xnx = xsx[n], xny = xsy[n], xnz = xsz[n];
    const float* __restrict__ Srow = g_S + ((size_t)h * N + n) * N;

    float sm = 0.f, ax = 0.f, ay = 0.f, az = 0.f;
    for (int m4 = lane * 4; m4 < N; m4 += 128) {
        float4 s4 = *(const float4*)(Srow + m4);
        float4 bx4 = *(const float4*)&xsx[m4];
        float4 by4 = *(const float4*)&xsy[m4];
        float4 bz4 = *(const float4*)&xsz[m4];
        float sv[4] = {s4.x, s4.y, s4.z, s4.w};
        float bx[4] = {bx4.x, bx4.y, bx4.z, bx4.w};
        float by[4] = {by4.x, by4.y, by4.z, by4.w};
        float bz[4] = {bz4.x, bz4.y, bz4.z, bz4.w};
        #pragma unroll
        for (int j = 0; j < 4; j++) {
            float dx = xnx - bx[j], dy = xny - by[j], dz = xnz - bz[j];
            float d2 = dx * dx + dy * dy + dz * dz;
            if (m4 + j == n) d2 = 1e-4f;
            float ee = __expf(sv[j] - 0.25f * d2);
            sm += ee;
            ax += ee * bx[j]; ay += ee * by[j]; az += ee * bz[j];
        }
    }
    #pragma unroll
    for (int o = 16; o; o >>= 1) {
        sm += __shfl_xor_sync(0xffffffffu, sm, o);
        ax += __shfl_xor_sync(0xffffffffu, ax, o);
        ay += __shfl_xor_sync(0xffffffffu, ay, o);
        az += __shfl_xor_sync(0xffffffffu, az, o);
    }
    if (lane == 0) {
        float inv = 1.f / sm;
        wred[h][0] = ax * inv; wred[h][1] = ay * inv; wred[h][2] = az * inv;
    }
    __syncthreads();
    if (t < 3) {
        float s = 0.f;
        #pragma unroll
        for (int hh = 0; hh < H; hh++) s += wred[hh][t];
        xout[n * 3 + t] = s * 0.125f;
    }
}

// ---------------- fused iter3 + feat (FFMA2, transposed P tile) ----------------
__global__ __launch_bounds__(256) void iter3_feat_kernel(const float* __restrict__ xin) {
    __shared__ __align__(16) float PsT[64][132];   // [j][r], rows packable as pairs
    __shared__ __align__(16) float Vs[64][36];
    __shared__ float xcx[64], xcy[64], xcz[64];
    int t = threadIdx.x;
    int h = blockIdx.y, z = blockIdx.z;
    int n0 = blockIdx.x * 128;

    // e-phase mapping: thread owns row er, half j0
    int er = t >> 1, j0 = (t & 1) * 32;
    float xr0 = xin[(n0 + er) * 3];
    float xr1 = xin[(n0 + er) * 3 + 1];
    float xr2 = xin[(n0 + er) * 3 + 2];
    // gemm mapping
    int dg = t & 7, rg = t >> 3;
    int d4 = dg * 4, r0 = rg * 4;
    u64 acc2[2][4] = {};   // [row-pair][d-col]
    float se = 0.f, sx = 0.f, sy = 0.f, sz = 0.f;

    for (int mb = 0; mb < MR; mb += 64) {
        int m0 = z * MR + mb;
        __syncthreads();  // previous gemm done with PsT/Vs
        #pragma unroll
        for (int i = 0; i < 8; i++) {
            int idx = i * 256 + t;
            int j = idx >> 5, d = idx & 31;
            Vs[j][d] = g_qkv[(size_t)(m0 + j) * QKV + 512 + h * DH + d];
        }
        if (t < 64)       xcx[t]       = xin[(m0 + t) * 3];
        else if (t < 128) xcy[t - 64]  = xin[(m0 + t - 64) * 3 + 1];
        else if (t < 192) xcz[t - 128] = xin[(m0 + t - 128) * 3 + 2];
        __syncthreads();  // xc ready for e-phase
        #pragma unroll
        for (int jj = 0; jj < 32; jj += 4) {
            float4 s4 = *(const float4*)&g_S[((size_t)h * N + n0 + er) * N + m0 + j0 + jj];
            float sv[4] = {s4.x, s4.y, s4.z, s4.w};
            #pragma unroll
            for (int c = 0; c < 4; c++) {
                int j = j0 + jj + c;
                float cxv = xcx[j], cyv = xcy[j], czv = xcz[j];
                float dx = xr0 - cxv, dy = xr1 - cyv, dz = xr2 - czv;
                float d2 = dx * dx + dy * dy + dz * dz;
                if (m0 + j == n0 + er) d2 = 1e-4f;
                float e = __expf(sv[c] - 0.25f * d2);
                PsT[j][er] = e;
                se += e;
                sx += e * cxv; sy += e * cyv; sz += e * czv;
            }
        }
        __syncthreads();  // PsT ready for gemm
        #pragma unroll 2
        for (int j = 0; j < 64; j++) {
            ulonglong2 pv = *(const ulonglong2*)&PsT[j][r0];  // rows r0..r0+3 packed
            float4 v = *(const float4*)&Vs[j][d4];
            u64 v0 = bcast2(v.x), v1 = bcast2(v.y), v2 = bcast2(v.z), v3 = bcast2(v.w);
            ffma2(acc2[0][0], pv.x, v0); ffma2(acc2[0][1], pv.x, v1);
            ffma2(acc2[0][2], pv.x, v2); ffma2(acc2[0][3], pv.x, v3);
            ffma2(acc2[1][0], pv.y, v0); ffma2(acc2[1][1], pv.y, v1);
            ffma2(acc2[1][2], pv.y, v2); ffma2(acc2[1][3], pv.y, v3);
        }
    }
    // pair-combine sums (threads t, t^1 share row er)
    se += __shfl_xor_sync(0xffffffffu, se, 1);
    sx += __shfl_xor_sync(0xffffffffu, sx, 1);
    sy += __shfl_xor_sync(0xffffffffu, sy, 1);
    sz += __shfl_xor_sync(0xffffffffu, sz, 1);
    if (!(t & 1)) {
        g_pse[z][h * N + n0 + er] = se;
        g_psx[z][h * N + n0 + er] = sx;
        g_psy[z][h * N + n0 + er] = sy;
        g_psz[z][h * N + n0 + er] = sz;
    }
    // partial (unnormalized) feat: unpack row-pairs
    float accf[4][4];
    #pragma unroll
    for (int dc = 0; dc < 4; dc++) {
        float2 p0 = unpack2(acc2[0][dc]);
        float2 p1 = unpack2(acc2[1][dc]);
        accf[0][dc] = p0.x; accf[1][dc] = p0.y;
        accf[2][dc] = p1.x; accf[3][dc] = p1.y;
    }
    #pragma unroll
    for (int i = 0; i < 4; i++) {
        float4 o;
        o.x = accf[i][0]; o.y = accf[i][1]; o.z = accf[i][2]; o.w = accf[i][3];
        *(float4*)&g_featP[z][(size_t)(n0 + r0 + i) * D + h * DH + d4] = o;
    }
}

// ---------------- combine feat partials, normalize ----------------
__global__ __launch_bounds__(256) void combine_feat_kernel() {
    int n = blockIdx.x;
    int c = threadIdx.x;
    int h = c >> 5;
    int idx = h * N + n;
    float inv = 1.f / (g_pse[0][idx] + g_pse[1][idx] + g_pse[2][idx]);
    size_t o = (size_t)n * D + c;
    g_feat[o] = (g_featP[0][o] + g_featP[1][o] + g_featP[2][o]) * inv;
}

// ---------------- launch ----------------
extern "C" void kernel_launch(void* const* d_in, const int* in_sizes, int n_in,
                              void* d_out, int out_size) {
    const float* x   = (const float*)d_in[0];
    const float* xyz = (const float*)d_in[1];
    const float* dy  = (const float*)d_in[2];
    const void*  dm  = d_in[3];
    const void*  bim = d_in[4];
    const float* Wq = (const float*)d_in[5];
    const float* bq = (const float*)d_in[6];
    const float* Wk = (const float*)d_in[7];
    const float* bk = (const float*)d_in[8];
    const float* Wv = (const float*)d_in[9];
    const float* bv = (const float*)d_in[10];
    const float* Wo = (const float*)d_in[11];
    const float* bo = (const float*)d_in[12];
    float* out = (float*)d_out;

    float *qkv, *wqkv, *bqkv, *feat, *xb;
    cudaGetSymbolAddress((void**)&qkv, g_qkv);
    cudaGetSymbolAddress((void**)&wqkv, g_Wqkv);
    cudaGetSymbolAddress((void**)&bqkv, g_bqkv);
    cudaGetSymbolAddress((void**)&feat, g_feat);
    cudaGetSymbolAddress((void**)&xb, g_xyz);
    float* xbuf0 = xb;
    float* xbuf1 = xb + N * 3;

    float* xyz_dst = xbuf0;
    float* out_dst = out;
    if (out_size == N * 3 + N * D) { xyz_dst = out; out_dst = out + N * 3; }
    else if (out_size == N * D)    { out_dst = out; }
    else if (out_size == N * 3)    { xyz_dst = out; out_dst = qkv; }

    detect_kernel<<<1, 256>>>((const unsigned char*)bim);
    bias_kernel<<<N, 256>>>(dy, dm, bim);
    pack_kernel<<<256, 256>>>(Wq, Wk, Wv, bq, bk, bv);

    gemm64<<<dim3(12, 48), 256>>>(x, wqkv, bqkv, nullptr, qkv, N, D, QKV);

    // fused score + iter1 (uses original xyz); 48 x-tiles of 64 rows
    score_iter1_kernel<<<dim3(48, 8, Z), 256>>>(xyz);
    combine_xyz_kernel<<<12, 256>>>(xbuf0);           // -> xyz1

    iter_kernel<<<N, 256>>>(xbuf0, xbuf1);            // -> xyz2

    // fused iter3 + feat (uses xyz2)
    iter3_feat_kernel<<<dim3(24, 8, Z), 256>>>(xbuf1);
    combine_xyz_kernel<<<12, 256>>>(xyz_dst);         // -> xyz3
    combine_feat_kernel<<<N, 256>>>();                // -> g_feat

    gemm64<<<dim3(4, 48), 256>>>(feat, Wo, bo, x, out_dst, N, D, D);
}

// round 10
// speedup vs baseline: 3.0121x; 1.1205x over previous
#include <cuda_runtime.h>
#include <cuda_fp16.h>
#include <math.h>
#include <stdint.h>

#define N 3072
#define D 256
#define H 8
#define DH 32
#define QKV 768
#define ZS 3        // score z-slices
#define MRS 1024
#define ZF 6        // feat z-slices
#define MRF 512

typedef unsigned long long u64;

// ---- packed f32x2 helpers (sm_103a) ----
__device__ __forceinline__ u64 bcast2(float v) {
    u64 r;
    asm("mov.b64 %0, {%1, %1};" : "=l"(r) : "f"(v));
    return r;
}
__device__ __forceinline__ void ffma2(u64& d, u64 a, u64 b) {
    asm("fma.rn.f32x2 %0, %1, %2, %3;" : "=l"(d) : "l"(a), "l"(b), "l"(d));
}
__device__ __forceinline__ float2 unpack2(u64 v) {
    float2 f;
    asm("mov.b64 {%0, %1}, %2;" : "=f"(f.x), "=f"(f.y) : "l"(v));
    return f;
}

// ---------------- scratch ----------------
__device__ float  g_qkv[N * QKV];
__device__ float  g_Wqkv[D * QKV];
__device__ float  g_bqkv[QKV];
__device__ float  g_feat[N * D];
__device__ __half g_S16[8ull * 3072ull * 3072ull];   // logits, fp16
__device__ float  g_bias[3072ull * 3072ull];
__device__ float  g_xyz[2][N * 3];
__device__ float  g_pse[ZF][H * N];
__device__ float  g_psx[ZF][H * N];
__device__ float  g_psy[ZF][H * N];
__device__ float  g_psz[ZF][H * N];
__device__ float  g_featP[ZF][N * D];
__device__ int    g_mask_mode;

// ---------------- mask dtype detection ----------------
__global__ void detect_kernel(const unsigned char* __restrict__ p) {
    __shared__ int c1, c3;
    int t = threadIdx.x;
    if (t == 0) { c1 = 0; c3 = 0; }
    __syncthreads();
    int l1 = 0, l3 = 0;
    for (int i = t; i < 16384; i += 256) {
        l1 += (p[i * 4 + 1] != 0);
        l3 += (p[i * 4 + 3] != 0);
    }
    atomicAdd(&c1, l1);
    atomicAdd(&c3, l3);
    __syncthreads();
    if (t == 0) g_mask_mode = (c3 == 0) ? 0 : ((c1 == 0) ? 1 : 2);
}

// ---------------- bias: B[n,m] = valid ? -delta_y : -1e30 ----------------
__global__ __launch_bounds__(256) void bias_kernel(const float* __restrict__ dy,
                                                   const void* __restrict__ dm,
                                                   const void* __restrict__ bim) {
    int n = blockIdx.x;
    int mode = g_mask_mode;
    size_t row = (size_t)n * N;
    for (int m = threadIdx.x; m < N; m += 256) {
        bool a, b;
        if (mode == 0) {
            a = ((const int*)dm)[row + m] != 0;
            b = ((const int*)bim)[row + m] != 0;
        } else if (mode == 1) {
            a = ((const float*)dm)[row + m] != 0.0f;
            b = ((const float*)bim)[row + m] != 0.0f;
        } else {
            a = ((const unsigned char*)dm)[row + m] != 0;
            b = ((const unsigned char*)bim)[row + m] != 0;
        }
        bool valid = (a && b) || (m == n);
        g_bias[row + m] = valid ? -dy[row + m] : -1e30f;
    }
}

// ---------------- pack [Wq|Wk|Wv] and biases ----------------
__global__ __launch_bounds__(256) void pack_kernel(const float* __restrict__ Wq,
                                                   const float* __restrict__ Wk,
                                                   const float* __restrict__ Wv,
                                                   const float* __restrict__ bq,
                                                   const float* __restrict__ bk,
                                                   const float* __restrict__ bv) {
    int idx = blockIdx.x * 256 + threadIdx.x;
    int row = idx >> 8, col = idx & 255;
    g_Wqkv[row * QKV + col]       = Wq[idx];
    g_Wqkv[row * QKV + 256 + col] = Wk[idx];
    g_Wqkv[row * QKV + 512 + col] = Wv[idx];
    if (idx < 256) {
        g_bqkv[idx]       = bq[idx];
        g_bqkv[256 + idx] = bk[idx];
        g_bqkv[512 + idx] = bv[idx];
    }
}

// ---------------- generic tiled GEMM (FFMA2 inner) ----------------
__global__ __launch_bounds__(256) void gemm64(const float* __restrict__ A,
                                              const float* __restrict__ W,
                                              const float* __restrict__ bias,
                                              const float* __restrict__ resid,
                                              float* __restrict__ C,
                                              int M, int K, int NN) {
    __shared__ __align__(16) float As[16][68];
    __shared__ __align__(16) float Ws[16][68];
    int t = threadIdx.x;
    int tx = t & 15, ty = t >> 4;
    int n0 = blockIdx.x * 64, m0 = blockIdx.y * 64;
    u64 acc2[2][4] = {};
    for (int kt = 0; kt < K; kt += 16) {
        #pragma unroll
        for (int i = 0; i < 4; i++) {
            int idx = i * 256 + t;
            int r = idx >> 4, kk = idx & 15;
            As[kk][r] = A[(size_t)(m0 + r) * K + kt + kk];
        }
        #pragma unroll
        for (int i = 0; i < 4; i++) {
            int idx = i * 256 + t;
            int kk = idx >> 6, j = idx & 63;
            Ws[kk][j] = W[(size_t)(kt + kk) * NN + n0 + j];
        }
        __syncthreads();
        #pragma unroll
        for (int kk = 0; kk < 16; kk++) {
            ulonglong2 av = *(const ulonglong2*)&As[kk][ty * 4];
            float4 b = *(const float4*)&Ws[kk][tx * 4];
            u64 b0 = bcast2(b.x), b1 = bcast2(b.y), b2 = bcast2(b.z), b3 = bcast2(b.w);
            ffma2(acc2[0][0], av.x, b0); ffma2(acc2[0][1], av.x, b1);
            ffma2(acc2[0][2], av.x, b2); ffma2(acc2[0][3], av.x, b3);
            ffma2(acc2[1][0], av.y, b0); ffma2(acc2[1][1], av.y, b1);
            ffma2(acc2[1][2], av.y, b2); ffma2(acc2[1][3], av.y, b3);
        }
        __syncthreads();
    }
    float acc[4][4];
    #pragma unroll
    for (int j = 0; j < 4; j++) {
        float2 p0 = unpack2(acc2[0][j]);
        float2 p1 = unpack2(acc2[1][j]);
        acc[0][j] = p0.x; acc[1][j] = p0.y;
        acc[2][j] = p1.x; acc[3][j] = p1.y;
    }
    #pragma unroll
    for (int i = 0; i < 4; i++) {
        int row = m0 + ty * 4 + i;
        #pragma unroll
        for (int j = 0; j < 4; j++) {
            int col = n0 + tx * 4 + j;
            float v = acc[i][j] + bias[col];
            if (resid) v += resid[(size_t)row * NN + col];
            C[(size_t)row * NN + col] = v;
        }
    }
}

// ---------------- fused score + iter1: 128x128 tile, 8x8/thread, fp16 S out ----------------
__global__ __launch_bounds__(256) void score_iter1_kernel(const float* __restrict__ xin) {
    __shared__ __align__(16) float Qs[32][132];
    __shared__ __align__(16) float Ks[32][132];
    __shared__ float xcx[128], xcy[128], xcz[128];
    int t = threadIdx.x;
    int h = blockIdx.y, z = blockIdx.z;
    int n0 = blockIdx.x * 128;
    int tx = t & 15, ty = t >> 4;

    #pragma unroll
    for (int i = 0; i < 16; i++) {
        int idx = i * 256 + t;
        int r = idx >> 5, d = idx & 31;
        Qs[d][r] = g_qkv[(size_t)(n0 + r) * QKV + h * DH + d];
    }
    float xrx[8], xry[8], xrz[8];
    #pragma unroll
    for (int i = 0; i < 8; i++) {
        int r = n0 + ty * 8 + i;
        xrx[i] = xin[r * 3]; xry[i] = xin[r * 3 + 1]; xrz[i] = xin[r * 3 + 2];
    }
    float se[8] = {}, sx[8] = {}, sy[8] = {}, sz[8] = {};
    const float sc = 0.17677669529663689f;  // 1/sqrt(32)

    for (int mb = 0; mb < MRS; mb += 128) {
        int m0 = z * MRS + mb;
        __syncthreads();
        #pragma unroll
        for (int i = 0; i < 16; i++) {
            int idx = i * 256 + t;
            int j = idx >> 5, d = idx & 31;
            Ks[d][j] = g_qkv[(size_t)(m0 + j) * QKV + 256 + h * DH + d];
        }
        if (t < 128) {
            xcx[t] = xin[(m0 + t) * 3];
            xcy[t] = xin[(m0 + t) * 3 + 1];
            xcz[t] = xin[(m0 + t) * 3 + 2];
        }
        __syncthreads();

        u64 acc2[4][8];
        #pragma unroll
        for (int p = 0; p < 4; p++)
            #pragma unroll
            for (int c = 0; c < 8; c++) acc2[p][c] = 0ull;

        #pragma unroll 8
        for (int kk = 0; kk < 32; kk++) {
            ulonglong2 a01 = *(const ulonglong2*)&Qs[kk][ty * 8];
            ulonglong2 a23 = *(const ulonglong2*)&Qs[kk][ty * 8 + 4];
            float4 b0 = *(const float4*)&Ks[kk][tx * 8];
            float4 b1 = *(const float4*)&Ks[kk][tx * 8 + 4];
            u64 av[4] = {a01.x, a01.y, a23.x, a23.y};
            u64 bb[8] = {bcast2(b0.x), bcast2(b0.y), bcast2(b0.z), bcast2(b0.w),
                         bcast2(b1.x), bcast2(b1.y), bcast2(b1.z), bcast2(b1.w)};
            #pragma unroll
            for (int p = 0; p < 4; p++)
                #pragma unroll
                for (int c = 0; c < 8; c++)
                    ffma2(acc2[p][c], av[p], bb[c]);
        }

        // epilogue: logits -> fp16 store + iter1 accumulation
        #pragma unroll
        for (int p = 0; p < 4; p++) {
            float2 pr[8];
            #pragma unroll
            for (int c = 0; c < 8; c++) pr[c] = unpack2(acc2[p][c]);
            #pragma unroll
            for (int hf = 0; hf < 2; hf++) {
                int i = p * 2 + hf;
                int r = n0 + ty * 8 + i;
                const float* brow = &g_bias[(size_t)r * N + m0 + tx * 8];
                float4 bi0 = *(const float4*)brow;
                float4 bi1 = *(const float4*)(brow + 4);
                float bb[8] = {bi0.x, bi0.y, bi0.z, bi0.w, bi1.x, bi1.y, bi1.z, bi1.w};
                float lgv[8];
                #pragma unroll
                for (int c = 0; c < 8; c++) {
                    int j = tx * 8 + c;
                    float a = hf ? pr[c].y : pr[c].x;
                    float lg = a * sc + bb[c];
                    lgv[c] = lg;
                    float dx = xrx[i] - xcx[j];
                    float dy = xry[i] - xcy[j];
                    float dz = xrz[i] - xcz[j];
                    float d2 = dx * dx + dy * dy + dz * dz;
                    if (m0 + j == r) d2 = 1e-4f;
                    float e = __expf(lg - 0.25f * d2);
                    se[i] += e;
                    sx[i] += e * xcx[j]; sy[i] += e * xcy[j]; sz[i] += e * xcz[j];
                }
                __half2 h01 = __floats2half2_rn(lgv[0], lgv[1]);
                __half2 h23 = __floats2half2_rn(lgv[2], lgv[3]);
                __half2 h45 = __floats2half2_rn(lgv[4], lgv[5]);
                __half2 h67 = __floats2half2_rn(lgv[6], lgv[7]);
                uint4 u;
                u.x = *(uint32_t*)&h01; u.y = *(uint32_t*)&h23;
                u.z = *(uint32_t*)&h45; u.w = *(uint32_t*)&h67;
                *(uint4*)&g_S16[((size_t)h * N + r) * N + m0 + tx * 8] = u;
            }
        }
    }
    #pragma unroll
    for (int i = 0; i < 8; i++) {
        #pragma unroll
        for (int o = 8; o; o >>= 1) {
            se[i] += __shfl_xor_sync(0xffffffffu, se[i], o);
            sx[i] += __shfl_xor_sync(0xffffffffu, sx[i], o);
            sy[i] += __shfl_xor_sync(0xffffffffu, sy[i], o);
            sz[i] += __shfl_xor_sync(0xffffffffu, sz[i], o);
        }
        if (tx == 0) {
            int r = n0 + ty * 8 + i;
            g_pse[z][h * N + r] = se[i];
            g_psx[z][h * N + r] = sx[i];
            g_psy[z][h * N + r] = sy[i];
            g_psz[z][h * N + r] = sz[i];
        }
    }
}

// ---------------- combine partial xyz sums -> new xyz ----------------
__global__ void combine_xyz_kernel(float* __restrict__ xout, int nz) {
    int n = blockIdx.x * 256 + threadIdx.x;
    float ox = 0.f, oy = 0.f, oz = 0.f;
    #pragma unroll
    for (int h = 0; h < H; h++) {
        int idx = h * N + n;
        float se = 0.f, ax = 0.f, ay = 0.f, az = 0.f;
        for (int zz = 0; zz < nz; zz++) {
            se += g_pse[zz][idx];
            ax += g_psx[zz][idx];
            ay += g_psy[zz][idx];
            az += g_psz[zz][idx];
        }
        float inv = 1.f / se;
        ox += ax * inv; oy += ay * inv; oz += az * inv;
    }
    xout[n * 3]     = ox * 0.125f;
    xout[n * 3 + 1] = oy * 0.125f;
    xout[n * 3 + 2] = oz * 0.125f;
}

// ---------------- iter2: streaming softmax mean-shift (fp16 S read) ----------------
__global__ __launch_bounds__(256) void iter_kernel(const float* __restrict__ xin,
                                                   float* __restrict__ xout) {
    __shared__ __align__(16) float xsx[N];
    __shared__ __align__(16) float xsy[N];
    __shared__ __align__(16) float xsz[N];
    __shared__ float wred[H][3];
    int t = threadIdx.x;
    for (int i = t; i < N; i += 256) {
        xsx[i] = xin[i * 3];
        xsy[i] = xin[i * 3 + 1];
        xsz[i] = xin[i * 3 + 2];
    }
    __syncthreads();

    int h = t >> 5, lane = t & 31;
    int n = blockIdx.x;
    float xnx = xsx[n], xny = xsy[n], xnz = xsz[n];
    const __half* __restrict__ Srow = g_S16 + ((size_t)h * N + n) * N;

    float sm = 0.f, ax = 0.f, ay = 0.f, az = 0.f;
    for (int m8 = lane * 8; m8 < N; m8 += 256) {
        uint4 hv = *(const uint4*)(Srow + m8);
        const __half2* hp = (const __half2*)&hv;
        float sv[8];
        #pragma unroll
        for (int c = 0; c < 4; c++) {
            float2 f = __half22float2(hp[c]);
            sv[c * 2] = f.x; sv[c * 2 + 1] = f.y;
        }
        #pragma unroll
        for (int j = 0; j < 8; j++) {
            int m = m8 + j;
            float bx = xsx[m], by = xsy[m], bz = xsz[m];
            float dx = xnx - bx, dy = xny - by, dz = xnz - bz;
            float d2 = dx * dx + dy * dy + dz * dz;
            if (m == n) d2 = 1e-4f;
            float ee = __expf(sv[j] - 0.25f * d2);
            sm += ee;
            ax += ee * bx; ay += ee * by; az += ee * bz;
        }
    }
    #pragma unroll
    for (int o = 16; o; o >>= 1) {
        sm += __shfl_xor_sync(0xffffffffu, sm, o);
        ax += __shfl_xor_sync(0xffffffffu, ax, o);
        ay += __shfl_xor_sync(0xffffffffu, ay, o);
        az += __shfl_xor_sync(0xffffffffu, az, o);
    }
    if (lane == 0) {
        float inv = 1.f / sm;
        wred[h][0] = ax * inv; wred[h][1] = ay * inv; wred[h][2] = az * inv;
    }
    __syncthreads();
    if (t < 3) {
        float s = 0.f;
        #pragma unroll
        for (int hh = 0; hh < H; hh++) s += wred[hh][t];
        xout[n * 3 + t] = s * 0.125f;
    }
}

// ---------------- fused iter3 + feat: 256-row tile, 8x4/thread, dyn smem ----------------
#define PST_STRIDE 260
__global__ __launch_bounds__(256) void iter3_feat_kernel(const float* __restrict__ xin) {
    extern __shared__ __align__(16) float smem_dyn[];
    float (*PsT)[PST_STRIDE] = (float(*)[PST_STRIDE])smem_dyn;          // [64][260]
    float (*Vs)[36] = (float(*)[36])(smem_dyn + 64 * PST_STRIDE);      // [64][36]
    float* xcx = smem_dyn + 64 * PST_STRIDE + 64 * 36;
    float* xcy = xcx + 64;
    float* xcz = xcy + 64;

    int t = threadIdx.x;
    int h = blockIdx.y, z = blockIdx.z;
    int n0 = blockIdx.x * 256;

    // e-phase: thread owns row er (all 64 cols of each m-step)
    int er = t;
    float xr0 = xin[(n0 + er) * 3];
    float xr1 = xin[(n0 + er) * 3 + 1];
    float xr2 = xin[(n0 + er) * 3 + 2];
    // gemm mapping: 8 rows x 4 cols
    int colg = t & 7, rowg = t >> 3;
    int d4 = colg * 4, r0 = rowg * 8;
    u64 acc2[4][4] = {};   // 4 row-pairs x 4 d-cols
    float se = 0.f, sx = 0.f, sy = 0.f, sz = 0.f;

    for (int mb = 0; mb < MRF; mb += 64) {
        int m0 = z * MRF + mb;
        __syncthreads();  // previous gemm done with PsT/Vs
        #pragma unroll
        for (int i = 0; i < 8; i++) {
            int idx = i * 256 + t;
            int j = idx >> 5, d = idx & 31;
            Vs[j][d] = g_qkv[(size_t)(m0 + j) * QKV + 512 + h * DH + d];
        }
        if (t < 64) {
            xcx[t] = xin[(m0 + t) * 3];
            xcy[t] = xin[(m0 + t) * 3 + 1];
            xcz[t] = xin[(m0 + t) * 3 + 2];
        }
        __syncthreads();  // Vs/xc ready
        const __half* Sr = &g_S16[((size_t)h * N + n0 + er) * N + m0];
        #pragma unroll
        for (int j8 = 0; j8 < 64; j8 += 8) {
            uint4 hv = *(const uint4*)(Sr + j8);
            const __half2* hp = (const __half2*)&hv;
            #pragma unroll
            for (int c2 = 0; c2 < 4; c2++) {
                float2 s2 = __half22float2(hp[c2]);
                float svv[2] = {s2.x, s2.y};
                #pragma unroll
                for (int k = 0; k < 2; k++) {
                    int j = j8 + c2 * 2 + k;
                    float cxv = xcx[j], cyv = xcy[j], czv = xcz[j];
                    float dx = xr0 - cxv, dy = xr1 - cyv, dz = xr2 - czv;
                    float d2 = dx * dx + dy * dy + dz * dz;
                    if (m0 + j == n0 + er) d2 = 1e-4f;
                    float e = __expf(svv[k] - 0.25f * d2);
                    PsT[j][er] = e;
                    se += e;
                    sx += e * cxv; sy += e * cyv; sz += e * czv;
                }
            }
        }
        __syncthreads();  // PsT ready
        #pragma unroll 4
        for (int j = 0; j < 64; j++) {
            ulonglong2 p01 = *(const ulonglong2*)&PsT[j][r0];
            ulonglong2 p23 = *(const ulonglong2*)&PsT[j][r0 + 4];
            float4 v = *(const float4*)&Vs[j][d4];
            u64 v0 = bcast2(v.x), v1 = bcast2(v.y), v2 = bcast2(v.z), v3 = bcast2(v.w);
            ffma2(acc2[0][0], p01.x, v0); ffma2(acc2[0][1], p01.x, v1);
            ffma2(acc2[0][2], p01.x, v2); ffma2(acc2[0][3], p01.x, v3);
            ffma2(acc2[1][0], p01.y, v0); ffma2(acc2[1][1], p01.y, v1);
            ffma2(acc2[1][2], p01.y, v2); ffma2(acc2[1][3], p01.y, v3);
            ffma2(acc2[2][0], p23.x, v0); ffma2(acc2[2][1], p23.x, v1);
            ffma2(acc2[2][2], p23.x, v2); ffma2(acc2[2][3], p23.x, v3);
            ffma2(acc2[3][0], p23.y, v0); ffma2(acc2[3][1], p23.y, v1);
            ffma2(acc2[3][2], p23.y, v2); ffma2(acc2[3][3], p23.y, v3);
        }
    }
    // per-row partial sums (unique row per thread)
    g_pse[z][h * N + n0 + er] = se;
    g_psx[z][h * N + n0 + er] = sx;
    g_psy[z][h * N + n0 + er] = sy;
    g_psz[z][h * N + n0 + er] = sz;
    // partial (unnormalized) feat: 8 rows x 4 cols
    #pragma unroll
    for (int p = 0; p < 4; p++) {
        float2 c0 = unpack2(acc2[p][0]);
        float2 c1 = unpack2(acc2[p][1]);
        float2 c2 = unpack2(acc2[p][2]);
        float2 c3 = unpack2(acc2[p][3]);
        int row0 = n0 + r0 + p * 2;
        float4 o0 = make_float4(c0.x, c1.x, c2.x, c3.x);
        float4 o1 = make_float4(c0.y, c1.y, c2.y, c3.y);
        *(float4*)&g_featP[z][(size_t)row0 * D + h * DH + d4] = o0;
        *(float4*)&g_featP[z][(size_t)(row0 + 1) * D + h * DH + d4] = o1;
    }
}

// ---------------- combine feat partials, normalize ----------------
__global__ __launch_bounds__(256) void combine_feat_kernel() {
    int n = blockIdx.x;
    int c = threadIdx.x;
    int h = c >> 5;
    int idx = h * N + n;
    float se = 0.f;
    #pragma unroll
    for (int zz = 0; zz < ZF; zz++) se += g_pse[zz][idx];
    float inv = 1.f / se;
    size_t o = (size_t)n * D + c;
    float s = 0.f;
    #pragma unroll
    for (int zz = 0; zz < ZF; zz++) s += g_featP[zz][o];
    g_feat[o] = s * inv;
}

// ---------------- launch ----------------
extern "C" void kernel_launch(void* const* d_in, const int* in_sizes, int n_in,
                              void* d_out, int out_size) {
    const float* x   = (const float*)d_in[0];
    const float* xyz = (const float*)d_in[1];
    const float* dy  = (const float*)d_in[2];
    const void*  dm  = d_in[3];
    const void*  bim = d_in[4];
    const float* Wq = (const float*)d_in[5];
    const float* bq = (const float*)d_in[6];
    const float* Wk = (const float*)d_in[7];
    const float* bk = (const float*)d_in[8];
    const float* Wv = (const float*)d_in[9];
    const float* bv = (const float*)d_in[10];
    const float* Wo = (const float*)d_in[11];
    const float* bo = (const float*)d_in[12];
    float* out = (float*)d_out;

    float *qkv, *wqkv, *bqkv, *feat, *xb;
    cudaGetSymbolAddress((void**)&qkv, g_qkv);
    cudaGetSymbolAddress((void**)&wqkv, g_Wqkv);
    cudaGetSymbolAddress((void**)&bqkv, g_bqkv);
    cudaGetSymbolAddress((void**)&feat, g_feat);
    cudaGetSymbolAddress((void**)&xb, g_xyz);
    float* xbuf0 = xb;
    float* xbuf1 = xb + N * 3;

    float* xyz_dst = xbuf0;
    float* out_dst = out;
    if (out_size == N * 3 + N * D) { xyz_dst = out; out_dst = out + N * 3; }
    else if (out_size == N * D)    { out_dst = out; }
    else if (out_size == N * 3)    { xyz_dst = out; out_dst = qkv; }

    const int feat_smem = (64 * PST_STRIDE + 64 * 36 + 192) * sizeof(float);
    cudaFuncSetAttribute(iter3_feat_kernel,
                         cudaFuncAttributeMaxDynamicSharedMemorySize, feat_smem);

    detect_kernel<<<1, 256>>>((const unsigned char*)bim);
    bias_kernel<<<N, 256>>>(dy, dm, bim);
    pack_kernel<<<256, 256>>>(Wq, Wk, Wv, bq, bk, bv);

    gemm64<<<dim3(12, 48), 256>>>(x, wqkv, bqkv, nullptr, qkv, N, D, QKV);

    // fused score + iter1: 24 n-tiles x 8 heads x 3 z-slices
    score_iter1_kernel<<<dim3(24, 8, ZS), 256>>>(xyz);
    combine_xyz_kernel<<<12, 256>>>(xbuf0, ZS);       // -> xyz1

    iter_kernel<<<N, 256>>>(xbuf0, xbuf1);            // -> xyz2

    // fused iter3 + feat: 12 n-tiles x 8 heads x 6 z-slices
    iter3_feat_kernel<<<dim3(12, 8, ZF), 256, feat_smem>>>(xbuf1);
    combine_xyz_kernel<<<12, 256>>>(xyz_dst, ZF);     // -> xyz3
    combine_feat_kernel<<<N, 256>>>();                // -> g_feat

    gemm64<<<dim3(4, 48), 256>>>(feat, Wo, bo, x, out_dst, N, D, D);
}